// round 1
// baseline (speedup 1.0000x reference)
#include <cuda_runtime.h>
#include <cuda_bf16.h>
#include <cstdint>

// ---------------- Problem constants ----------------
#define QLEN   2048
#define DMODEL 4096
#define NHEAD  32
#define NKVH   8
#define HEADD  128
#define NSINK  4
#define NWIN   2048
#define NSNW   (NSINK + NWIN)          // 2052
#define KTOT   (NSNW + QLEN)           // 4100
#define GRP    (NHEAD / NKVH)          // 4
#define KVDIM  (NKVH * HEADD)          // 1024

#define NEG_BIG (-3.4028234663852886e38f)   // finfo(float32).min
#define LOG10000_OVER_64 0.14391156831212787f
#define ATTN_SCALE 0.08838834764831845f     // 1/sqrt(128)

// ---------------- Scratch (device globals; no runtime alloc) ----------------
__device__ float g_q[QLEN * DMODEL];        // q projection, then RoPE'd in place
__device__ float g_kproj[QLEN * KVDIM];
__device__ float g_vproj[QLEN * KVDIM];
__device__ float g_K[NKVH * KTOT * HEADD];  // concatenated, RoPE'd K cache
__device__ float g_V[NKVH * KTOT * HEADD];
__device__ float g_attn[QLEN * DMODEL];     // attention output (pre-Wo)
__device__ float g_bias[NSNW];              // cache bias (mask * NEG)
__device__ int   g_maxpos;

__device__ __forceinline__ float neg_inf() { return __int_as_float(0xff800000u); }

// ---------------- max position + bias precompute ----------------
__global__ void maxpos_kernel(const int* __restrict__ sink_pos,
                              const int* __restrict__ key_pos) {
    __shared__ int sm[256];
    int tid = threadIdx.x;
    int v = -2147483647;
    for (int i = tid; i < NWIN; i += 256) v = max(v, key_pos[i]);
    for (int i = tid; i < NSINK; i += 256) v = max(v, sink_pos[i]);
    sm[tid] = v;
    __syncthreads();
    for (int s = 128; s > 0; s >>= 1) {
        if (tid < s) sm[tid] = max(sm[tid], sm[tid + s]);
        __syncthreads();
    }
    if (tid == 0) g_maxpos = sm[0] + 1;
}

__global__ void bias_kernel(const float* __restrict__ sink_mask,
                            const float* __restrict__ key_mask) {
    int i = blockIdx.x * blockDim.x + threadIdx.x;
    if (i >= NSNW) return;
    float m = (i < NSINK) ? sink_mask[i] : key_mask[i - NSINK];
    g_bias[i] = m * NEG_BIG;
}

// ---------------- classic SGEMM: C[M,N] = A[M,K] @ B[K,N], all row-major ----------------
// 128x128 block tile, K-step 8, 256 threads, 8x8 per-thread micro tile.
// Requires M%128==0, N%128==0, K%8==0 (true for all calls here).
__global__ void __launch_bounds__(256) sgemm128(
    const float* __restrict__ A, const float* __restrict__ B,
    float* __restrict__ C, int M, int N, int K) {
    __shared__ float As[8][128];
    __shared__ float Bs[8][128];

    const int tid  = threadIdx.x;
    const int cRow = blockIdx.y * 128;
    const int cCol = blockIdx.x * 128;

    const int aRow = tid >> 1;               // 0..127
    const int aCol = (tid & 1) * 4;          // 0 or 4
    const int bRow = tid >> 5;               // 0..7
    const int bCol = (tid & 31) * 4;         // 0..124
    const int tRow = (tid >> 4) * 8;         // 0..120
    const int tCol = (tid & 15) * 8;

    float acc[8][8];
#pragma unroll
    for (int i = 0; i < 8; i++)
#pragma unroll
        for (int j = 0; j < 8; j++) acc[i][j] = 0.f;

    for (int k0 = 0; k0 < K; k0 += 8) {
        float4 a = *(const float4*)(A + (size_t)(cRow + aRow) * K + k0 + aCol);
        As[aCol + 0][aRow] = a.x;
        As[aCol + 1][aRow] = a.y;
        As[aCol + 2][aRow] = a.z;
        As[aCol + 3][aRow] = a.w;
        *(float4*)(&Bs[bRow][bCol]) =
            *(const float4*)(B + (size_t)(k0 + bRow) * N + cCol + bCol);
        __syncthreads();

#pragma unroll
        for (int kk = 0; kk < 8; kk++) {
            float4 m0 = *(const float4*)(&As[kk][tRow]);
            float4 m1 = *(const float4*)(&As[kk][tRow + 4]);
            float4 n0 = *(const float4*)(&Bs[kk][tCol]);
            float4 n1 = *(const float4*)(&Bs[kk][tCol + 4]);
            float rm[8] = {m0.x, m0.y, m0.z, m0.w, m1.x, m1.y, m1.z, m1.w};
            float rn[8] = {n0.x, n0.y, n0.z, n0.w, n1.x, n1.y, n1.z, n1.w};
#pragma unroll
            for (int i = 0; i < 8; i++)
#pragma unroll
                for (int j = 0; j < 8; j++) acc[i][j] = fmaf(rm[i], rn[j], acc[i][j]);
        }
        __syncthreads();
    }

#pragma unroll
    for (int i = 0; i < 8; i++) {
        float4 v0 = {acc[i][0], acc[i][1], acc[i][2], acc[i][3]};
        float4 v1 = {acc[i][4], acc[i][5], acc[i][6], acc[i][7]};
        float* cp = C + (size_t)(cRow + tRow + i) * N + cCol + tCol;
        *(float4*)cp       = v0;
        *(float4*)(cp + 4) = v1;
    }
}

// ---------------- RoPE on q (in place). One thread per (token, head, pair) ----------------
__global__ void rope_q_kernel() {
    int idx = blockIdx.x * blockDim.x + threadIdx.x;
    if (idx >= QLEN * NHEAD * 64) return;
    int i  = idx & 63;
    int hq = idx >> 6;
    int h  = hq & (NHEAD - 1);
    int t  = hq >> 5;                     // NHEAD == 32
    float* p = g_q + (size_t)t * DMODEL + h * HEADD;
    float pos = (float)(g_maxpos + t);
    float freq = expf(-(float)i * LOG10000_OVER_64);
    float ang = pos * freq;
    float c, s;
    sincosf(ang, &s, &c);
    float x1 = p[i], x2 = p[i + 64];
    p[i]      = x1 * c - x2 * s;
    p[i + 64] = x2 * c + x1 * s;
}

// ---------------- Build concatenated K (RoPE'd) and V caches ----------------
__global__ void build_cache_kernel(const float* __restrict__ sink_k,
                                   const float* __restrict__ sink_v,
                                   const float* __restrict__ win_k,
                                   const float* __restrict__ win_v,
                                   const int* __restrict__ sink_pos,
                                   const int* __restrict__ key_pos) {
    int idx = blockIdx.x * blockDim.x + threadIdx.x;
    if (idx >= NKVH * KTOT * 64) return;
    int i   = idx & 63;
    int rj  = idx >> 6;
    int j   = rj % KTOT;
    int kvh = rj / KTOT;

    const float* kp;
    const float* vp;
    int pos;
    if (j < NSINK) {
        kp = sink_k + (size_t)(kvh * NSINK + j) * HEADD;
        vp = sink_v + (size_t)(kvh * NSINK + j) * HEADD;
        pos = sink_pos[j];
    } else if (j < NSNW) {
        int w = j - NSINK;
        kp = win_k + (size_t)(kvh * NWIN + w) * HEADD;
        vp = win_v + (size_t)(kvh * NWIN + w) * HEADD;
        pos = key_pos[w];
    } else {
        int t = j - NSNW;
        kp = g_kproj + (size_t)t * KVDIM + kvh * HEADD;
        vp = g_vproj + (size_t)t * KVDIM + kvh * HEADD;
        pos = g_maxpos + t;
    }

    float freq = expf(-(float)i * LOG10000_OVER_64);
    float ang = (float)pos * freq;
    float c, s;
    sincosf(ang, &s, &c);
    float x1 = kp[i], x2 = kp[i + 64];

    size_t out = ((size_t)kvh * KTOT + j) * HEADD;
    g_K[out + i]      = x1 * c - x2 * s;
    g_K[out + i + 64] = x2 * c + x1 * s;
    g_V[out + i]      = vp[i];
    g_V[out + i + 64] = vp[i + 64];
}

// ---------------- Attention: warp per query row, online softmax, 32-key smem chunks ----------------
__global__ void __launch_bounds__(256) attn_kernel() {
    __shared__ float4 Ks[32][32];   // 32 keys x 128 dims
    __shared__ float4 Vs[32][32];

    const int h    = blockIdx.x;
    const int kvh  = h >> 2;                     // GRP = 4
    const int warp = threadIdx.x >> 5;
    const int lane = threadIdx.x & 31;
    const int qt   = blockIdx.y * 8 + warp;      // query token

    const float* qp = g_q + (size_t)qt * DMODEL + h * HEADD;
    float4 qf = *(const float4*)(qp + lane * 4);

    float4 o = {0.f, 0.f, 0.f, 0.f};
    float m = neg_inf(), l = 0.f;

    const int kmaxBlock = NSNW + (blockIdx.y * 8 + 7) + 1; // keys the block needs
    const float* Kbase = g_K + (size_t)kvh * KTOT * HEADD;
    const float* Vbase = g_V + (size_t)kvh * KTOT * HEADD;

    for (int c0 = 0; c0 < kmaxBlock; c0 += 32) {
        // cooperative chunk load
        for (int ii = threadIdx.x; ii < 32 * 32; ii += 256) {
            int r = ii >> 5, c = ii & 31;
            int j = c0 + r;
            if (j < KTOT) {
                Ks[r][c] = *(const float4*)(Kbase + (size_t)j * HEADD + c * 4);
                Vs[r][c] = *(const float4*)(Vbase + (size_t)j * HEADD + c * 4);
            } else {
                Ks[r][c] = make_float4(0.f, 0.f, 0.f, 0.f);
                Vs[r][c] = make_float4(0.f, 0.f, 0.f, 0.f);
            }
        }
        __syncthreads();

        float sc[32];
        float cmax = neg_inf();
#pragma unroll
        for (int k = 0; k < 32; k++) {
            int j = c0 + k;
            float4 kf = Ks[k][lane];
            float p = qf.x * kf.x + qf.y * kf.y + qf.z * kf.z + qf.w * kf.w;
            p += __shfl_xor_sync(0xffffffffu, p, 16);
            p += __shfl_xor_sync(0xffffffffu, p, 8);
            p += __shfl_xor_sync(0xffffffffu, p, 4);
            p += __shfl_xor_sync(0xffffffffu, p, 2);
            p += __shfl_xor_sync(0xffffffffu, p, 1);
            float b;
            if (j < NSNW) b = g_bias[j];
            else          b = (j - NSNW <= qt) ? 0.f : neg_inf();
            float sval = p * ATTN_SCALE + b;
            sc[k] = sval;
            cmax = fmaxf(cmax, sval);
        }

        float mn = fmaxf(m, cmax);
        if (mn != neg_inf()) {
            float r = (m == neg_inf()) ? 0.f : __expf(m - mn);
            l *= r;
            o.x *= r; o.y *= r; o.z *= r; o.w *= r;
#pragma unroll
            for (int k = 0; k < 32; k++) {
                float p = __expf(sc[k] - mn);   // -inf -> 0
                float4 vf = Vs[k][lane];
                l += p;
                o.x = fmaf(p, vf.x, o.x);
                o.y = fmaf(p, vf.y, o.y);
                o.z = fmaf(p, vf.z, o.z);
                o.w = fmaf(p, vf.w, o.w);
            }
            m = mn;
        }
        __syncthreads();
    }

    float inv = 1.f / l;
    o.x *= inv; o.y *= inv; o.z *= inv; o.w *= inv;
    *(float4*)(g_attn + (size_t)qt * DMODEL + h * HEADD + lane * 4) = o;
}

// ---------------- launch ----------------
extern "C" void kernel_launch(void* const* d_in, const int* in_sizes, int n_in,
                              void* d_out, int out_size) {
    const float* hidden    = (const float*)d_in[0];
    const float* sink_k    = (const float*)d_in[1];
    const float* sink_v    = (const float*)d_in[2];
    const float* win_k     = (const float*)d_in[3];
    const float* win_v     = (const float*)d_in[4];
    const int*   sink_pos  = (const int*)d_in[5];
    const int*   key_pos   = (const int*)d_in[6];
    const float* sink_mask = (const float*)d_in[7];
    const float* key_mask  = (const float*)d_in[8];
    const float* Wq        = (const float*)d_in[9];
    const float* Wk        = (const float*)d_in[10];
    const float* Wv        = (const float*)d_in[11];
    const float* Wo        = (const float*)d_in[12];
    float*       out       = (float*)d_out;

    float *pq, *pk, *pv, *pattn;
    cudaGetSymbolAddress((void**)&pq, g_q);
    cudaGetSymbolAddress((void**)&pk, g_kproj);
    cudaGetSymbolAddress((void**)&pv, g_vproj);
    cudaGetSymbolAddress((void**)&pattn, g_attn);

    maxpos_kernel<<<1, 256>>>(sink_pos, key_pos);
    bias_kernel<<<(NSNW + 255) / 256, 256>>>(sink_mask, key_mask);

    // projections
    sgemm128<<<dim3(DMODEL / 128, QLEN / 128), 256>>>(hidden, Wq, pq, QLEN, DMODEL, DMODEL);
    sgemm128<<<dim3(KVDIM / 128, QLEN / 128), 256>>>(hidden, Wk, pk, QLEN, KVDIM, DMODEL);
    sgemm128<<<dim3(KVDIM / 128, QLEN / 128), 256>>>(hidden, Wv, pv, QLEN, KVDIM, DMODEL);

    // RoPE + cache assembly
    rope_q_kernel<<<(QLEN * NHEAD * 64 + 255) / 256, 256>>>();
    build_cache_kernel<<<(NKVH * KTOT * 64 + 255) / 256, 256>>>(
        sink_k, sink_v, win_k, win_v, sink_pos, key_pos);

    // attention
    attn_kernel<<<dim3(NHEAD, QLEN / 8), 256>>>();

    // output projection
    sgemm128<<<dim3(DMODEL / 128, QLEN / 128), 256>>>(pattn, Wo, out, QLEN, DMODEL, DMODEL);
}